// round 13
// baseline (speedup 1.0000x reference)
#include <cuda_runtime.h>
#include <math.h>

// B=32, C=32, H=64, W=64, pool 2x2 -> 32x32 pooled positions per channel.
// Grid 2048 = slab(1024 = c x h2) x 2 batch-halves; block = 128 thr (4 warps).
// Warp wq of half h covers i in [16h + 4wq, 16h + 4wq + 4); lane = w2.
// 9 linear batch-sums per position; halves merge through g_half; the
// second-arriving block per slab does the nonlinear combine (fixed order ->
// deterministic) and atomicAdds a double; 1024th combiner writes out.

__device__ float g_half[2048][32][9];      // per-block merged partial sums
__device__ unsigned int g_cnt[1024];       // per-slab arrival counters (self-reset)
__device__ double g_acc = 0.0;             // final accumulator (self-reset)
__device__ unsigned int g_count = 0;       // combine counter (self-reset)

// exp(x) on the FMA/ALU pipes, ~4e-5 rel err for |x| < 30.
__device__ __forceinline__ float fexp(float x) {
    float t  = x * 1.4426950408889634f;
    float fr = t + 12582912.0f;               // round via 1.5*2^23
    int   n  = __float_as_int(fr) - 0x4B400000;
    float f  = t - (fr - 12582912.0f);        // frac in [-0.5, 0.5]
    float p  = 0.009618130f;
    p = fmaf(p, f, 0.055504109f);
    p = fmaf(p, f, 0.240226507f);
    p = fmaf(p, f, 0.693147181f);
    p = fmaf(p, f, 1.0f);
    return __int_as_float(__float_as_int(p) + (n << 23));
}

__global__ __launch_bounds__(128, 10) void k_main(
    const float* __restrict__ mu_a, const float* __restrict__ lv_a,
    const float* __restrict__ mu_b, const float* __restrict__ lv_b,
    float* __restrict__ out)
{
    __shared__ float s_p[4][32][9];    // [warp][lane=w2][sum]

    const int t    = threadIdx.x;
    const int lane = t & 31;           // w2
    const int wq   = t >> 5;           // 0..3
    const int b    = blockIdx.x;
    const int slab = b >> 1;           // (c, h2)
    const int half = b & 1;
    const int c    = slab >> 5;
    const int h2   = slab & 31;

    const int istride = 32 * 64 * 64;  // batch stride (floats)
    int ofs = (16 * half + 4 * wq) * istride + (c * 64 + 2 * h2) * 64 + 2 * lane;

    float A[9];
    #pragma unroll
    for (int k = 0; k < 9; k++) A[k] = 0.f;

    #pragma unroll
    for (int i = 0; i < 4; i++) {
        float2 A0  = *(const float2*)(mu_a + ofs);
        float2 A1  = *(const float2*)(mu_a + ofs + 64);
        float2 La0 = *(const float2*)(lv_a + ofs);
        float2 La1 = *(const float2*)(lv_a + ofs + 64);
        float2 B0  = *(const float2*)(mu_b + ofs);
        float2 B1  = *(const float2*)(mu_b + ofs + 64);
        float2 Lb0 = *(const float2*)(lv_b + ofs);
        float2 Lb1 = *(const float2*)(lv_b + ofs + 64);
        ofs += istride;

        float ma = (A0.x + A0.y + A1.x + A1.y) * 0.25f;
        float mb = (B0.x + B0.y + B1.x + B1.y) * 0.25f;
        // 2 exps on MUFU + 2 on FMA pipe per quad
        float sa = (__expf(La0.x) + fexp(La0.y)) + (__expf(La1.x) + fexp(La1.y));
        float sb = (__expf(Lb0.x) + fexp(Lb0.y)) + (__expf(Lb1.x) + fexp(Lb1.y));

        float ma2 = ma * ma, mb2 = mb * mb;
        float ra = __frcp_rn(sa); float ra2 = ra * ra;   // 1/v^2 = 256*ra2
        float rb = __frcp_rn(sb); float rb2 = rb * rb;

        A[0] += ma;
        A[1] += fmaf(sa * sa, 0.00390625f, ma2);         // ma^2 + (sa/16)^2
        A[2] += ra2; A[3] += ma * ra2; A[4] += ma2 * ra2;
        A[5] += rb2; A[6] += mb * rb2; A[7] += mb2 * rb2;
        A[8] += __logf(sb) - __logf(sa);                 // la - lb (consts cancel)
    }

    #pragma unroll
    for (int k = 0; k < 9; k++) s_p[wq][lane][k] = A[k];
    __syncthreads();

    if (wq == 0) {
        // merge this block's 4 warps, publish to g_half[b]
        #pragma unroll
        for (int k = 0; k < 9; k++)
            g_half[b][lane][k] =
                s_p[0][lane][k] + s_p[1][lane][k] + s_p[2][lane][k] + s_p[3][lane][k];
        __threadfence();

        unsigned int prev = 0;
        if (lane == 0) prev = atomicInc(&g_cnt[slab], 0xffffffffu);
        prev = __shfl_sync(0xffffffffu, prev, 0);

        if (prev == 1) {   // second arrival: do the slab combine
            __threadfence();   // acquire: make peer half's g_half visible
            float m[9];
            #pragma unroll
            for (int k = 0; k < 9; k++)
                m[k] = g_half[2 * slab][lane][k] + g_half[2 * slab + 1][lane][k];

            // sum_ij diff = 32*L - 256*[0.5*SS*U0a - S1*U1a + 16*U2a]
            //                    + 256*[0.5*SS*U0b - S1*U1b + 16*U2b]
            float pa = 0.5f * m[1] * m[2] - m[0] * m[3] + 16.0f * m[4];
            float pb = 0.5f * m[1] * m[5] - m[0] * m[6] + 16.0f * m[7];
            double contrib = 32.0 * (double)m[8] + 256.0 * ((double)pb - (double)pa);

            #pragma unroll
            for (int o = 16; o; o >>= 1)
                contrib += __shfl_xor_sync(0xffffffffu, contrib, o);

            if (lane == 0) {
                g_cnt[slab] = 0;                       // reset for next replay
                atomicAdd(&g_acc, contrib);
                __threadfence();
                unsigned int done = atomicInc(&g_count, 0xffffffffu);
                if (done == 1023) {                    // last combine
                    out[0] = (float)(g_acc * (1.0 / 1024.0));   // /(B*B)
                    g_acc = 0.0;
                    g_count = 0;
                }
            }
        }
    }
}

extern "C" void kernel_launch(void* const* d_in, const int* in_sizes, int n_in,
                              void* d_out, int out_size) {
    const float* mu_a = (const float*)d_in[0];
    const float* lv_a = (const float*)d_in[1];
    const float* mu_b = (const float*)d_in[2];
    const float* lv_b = (const float*)d_in[3];

    k_main<<<2048, 128>>>(mu_a, lv_a, mu_b, lv_b, (float*)d_out);
}

// round 14
// speedup vs baseline: 1.2159x; 1.2159x over previous
#include <cuda_runtime.h>
#include <math.h>
#include <stdint.h>

// B=32, C=32, H=64, W=64, pool 2x2 -> 32x32 pooled positions per channel.
// Block (128 thr) owns one (c,h2) slab. The 2 pooled rows are CONTIGUOUS in
// gmem: per tensor per i, the slab is one 512B segment.
// cp.async pipeline: ring of 3 chunks, chunk = 4 batch indices x 4 tensors x
// 512B (8KB). Thread (q=t>>5, l=t&31) stages 16B of tensor q per i.
// Compute: warp wq processes i = 4*ch + wq from smem; 9 linear batch-sums.
// Epilogue: smem merge -> nonlinear combine -> double atomicAdd; last block
// writes out (self-resetting counters, graph-replay safe).

__device__ double g_acc = 0.0;
__device__ unsigned int g_count = 0;

// exp(x) on the FMA/ALU pipes, ~4e-5 rel err for |x| < 30.
__device__ __forceinline__ float fexp(float x) {
    float t  = x * 1.4426950408889634f;
    float fr = t + 12582912.0f;               // round via 1.5*2^23
    int   n  = __float_as_int(fr) - 0x4B400000;
    float f  = t - (fr - 12582912.0f);        // frac in [-0.5, 0.5]
    float p  = 0.009618130f;
    p = fmaf(p, f, 0.055504109f);
    p = fmaf(p, f, 0.240226507f);
    p = fmaf(p, f, 0.693147181f);
    p = fmaf(p, f, 1.0f);
    return __int_as_float(__float_as_int(p) + (n << 23));
}

#define NSTAGE 3

__device__ __forceinline__ uint32_t smem_u32(const void* p) {
    return (uint32_t)__cvta_generic_to_shared(p);
}
#define CP16(saddr, gptr) \
    asm volatile("cp.async.cg.shared.global [%0], [%1], 16;" :: "r"(saddr), "l"(gptr))
#define CP_COMMIT() asm volatile("cp.async.commit_group;")
#define CP_WAIT(N)  asm volatile("cp.async.wait_group %0;" :: "n"(N))

__global__ __launch_bounds__(128, 7) void k_main(
    const float* __restrict__ mu_a, const float* __restrict__ lv_a,
    const float* __restrict__ mu_b, const float* __restrict__ lv_b,
    float* __restrict__ out)
{
    __shared__ __align__(16) float s_buf[NSTAGE][4][4][128]; // [slot][i_sub][tensor][2 rows x 64]
    __shared__ float s_p[4][32][9];
    __shared__ bool  s_last;

    const int t    = threadIdx.x;
    const int lane = t & 31;
    const int wq   = t >> 5;           // staging: tensor id; compute: i_sub
    const int b    = blockIdx.x;
    const int c    = b >> 5;
    const int h2   = b & 31;
    const int istride = 32 * 64 * 64;  // batch stride (floats)
    const int slab = (c * 64 + 2 * h2) * 64;   // 128 consecutive floats (2 rows)

    // staging source: this thread's tensor, 16B segment 4*lane of the 512B slab
    const float* gbase =
        (wq == 0 ? mu_a : wq == 1 ? lv_a : wq == 2 ? mu_b : lv_b) + slab + 4 * lane;

    float A[9];
    #pragma unroll
    for (int k = 0; k < 9; k++) A[k] = 0.f;

    // prefetch chunks 0..NSTAGE-1
    #pragma unroll
    for (int ch = 0; ch < NSTAGE; ch++) {
        #pragma unroll
        for (int o = 0; o < 4; o++) {
            uint32_t dst = smem_u32(&s_buf[ch][o][wq][4 * lane]);
            CP16(dst, gbase + (4 * ch + o) * (long)istride);
        }
        CP_COMMIT();
    }

    #pragma unroll
    for (int ch = 0; ch < 8; ch++) {
        CP_WAIT(NSTAGE - 1);           // oldest pending chunk (== ch) has landed
        __syncthreads();

        // compute i = 4*ch + wq from smem
        {
            const int slot = ch % NSTAGE;
            const float* base = &s_buf[slot][wq][0][0];   // [4][128]
            float2 A0  = *(const float2*)(base +   0 + 2 * lane);
            float2 A1  = *(const float2*)(base +  64 + 2 * lane);
            float2 La0 = *(const float2*)(base + 128 + 2 * lane);
            float2 La1 = *(const float2*)(base + 192 + 2 * lane);
            float2 B0  = *(const float2*)(base + 256 + 2 * lane);
            float2 B1  = *(const float2*)(base + 320 + 2 * lane);
            float2 Lb0 = *(const float2*)(base + 384 + 2 * lane);
            float2 Lb1 = *(const float2*)(base + 448 + 2 * lane);

            float ma = (A0.x + A0.y + A1.x + A1.y) * 0.25f;
            float mb = (B0.x + B0.y + B1.x + B1.y) * 0.25f;
            // 2 exps on MUFU + 2 on FMA pipe per quad
            float sa = (__expf(La0.x) + fexp(La0.y)) + (__expf(La1.x) + fexp(La1.y));
            float sb = (__expf(Lb0.x) + fexp(Lb0.y)) + (__expf(Lb1.x) + fexp(Lb1.y));

            float ma2 = ma * ma, mb2 = mb * mb;
            float ra = __frcp_rn(sa); float ra2 = ra * ra;   // 1/v^2 = 256*ra2
            float rb = __frcp_rn(sb); float rb2 = rb * rb;

            A[0] += ma;
            A[1] += fmaf(sa * sa, 0.00390625f, ma2);         // ma^2 + (sa/16)^2
            A[2] += ra2; A[3] += ma * ra2; A[4] += ma2 * ra2;
            A[5] += rb2; A[6] += mb * rb2; A[7] += mb2 * rb2;
            A[8] += __logf(sb) - __logf(sa);                 // la - lb
        }

        __syncthreads();               // all reads of slot done before reuse

        if (ch + NSTAGE < 8) {
            const int nch  = ch + NSTAGE;
            const int slot = nch % NSTAGE;
            #pragma unroll
            for (int o = 0; o < 4; o++) {
                uint32_t dst = smem_u32(&s_buf[slot][o][wq][4 * lane]);
                CP16(dst, gbase + (4 * nch + o) * (long)istride);
            }
        }
        CP_COMMIT();                   // empty commits keep group accounting aligned
    }

    #pragma unroll
    for (int k = 0; k < 9; k++) s_p[wq][lane][k] = A[k];
    __syncthreads();

    if (wq == 0) {
        float m[9];
        #pragma unroll
        for (int k = 0; k < 9; k++)
            m[k] = s_p[0][lane][k] + s_p[1][lane][k] + s_p[2][lane][k] + s_p[3][lane][k];

        // sum_ij diff = 32*L - 256*[0.5*SS*U0a - S1*U1a + 16*U2a]
        //                    + 256*[0.5*SS*U0b - S1*U1b + 16*U2b]
        float pa = 0.5f * m[1] * m[2] - m[0] * m[3] + 16.0f * m[4];
        float pb = 0.5f * m[1] * m[5] - m[0] * m[6] + 16.0f * m[7];
        double contrib = 32.0 * (double)m[8] + 256.0 * ((double)pb - (double)pa);

        #pragma unroll
        for (int o = 16; o; o >>= 1)
            contrib += __shfl_xor_sync(0xffffffffu, contrib, o);

        if (lane == 0) {
            atomicAdd(&g_acc, contrib);
            __threadfence();
            unsigned int prev = atomicInc(&g_count, 0xffffffffu);
            s_last = (prev == gridDim.x - 1);
        }
    }
    __syncthreads();

    if (s_last && t == 0) {
        out[0] = (float)(g_acc * (1.0 / 1024.0));   // /(B*B)
        g_acc = 0.0;                                // reset for next replay
        g_count = 0;
    }
}

extern "C" void kernel_launch(void* const* d_in, const int* in_sizes, int n_in,
                              void* d_out, int out_size) {
    const float* mu_a = (const float*)d_in[0];
    const float* lv_a = (const float*)d_in[1];
    const float* mu_b = (const float*)d_in[2];
    const float* lv_b = (const float*)d_in[3];

    k_main<<<1024, 128>>>(mu_a, lv_a, mu_b, lv_b, (float*)d_out);
}